// round 12
// baseline (speedup 1.0000x reference)
#include <cuda_runtime.h>
#include <cuda_bf16.h>
#include <cstdint>

// ---------------------------------------------------------------------------
// Problem dims
// ---------------------------------------------------------------------------
#define BATCH   128
#define TSTEPS  32
#define D_DIM   6400
#define HID     1000
#define ACT     4
#define M_DIM   (BATCH * TSTEPS)   // 4096
#define N_DIM   HID                // 1000
#define N_PAD   1024
#define K_DIM   D_DIM              // 6400

#define BETA_F  0.99f
#define THR_F   1.0f
#define TOL_F   2.5e-4f            // borderline margin -> exact fp32 recompute
#define FLAG_CAP 65536

// ---------------------------------------------------------------------------
// Global scratch (no big split arrays anymore — conversion is inline)
// ---------------------------------------------------------------------------
__device__ uint32_t g_spk1[M_DIM * 32];                   // bit-packed spk1
__device__ int      g_nflag;                              // zero-init; layer2 resets
__device__ int      g_flag[FLAG_CAP];                     // packed (b<<10)|h

// ---------------------------------------------------------------------------
// Helpers
// ---------------------------------------------------------------------------
__device__ __forceinline__ uint32_t smem_to_u32(const void* p) {
    uint32_t a;
    asm("{ .reg .u64 t; cvta.to.shared.u64 t, %1; cvt.u32.u64 %0, t; }" : "=r"(a) : "l"(p));
    return a;
}

// 2-way bf16 split of two fp32 values packed as bf16x2 (lo = elem a, hi = elem b).
__device__ __forceinline__ void split2(float a, float b, uint32_t& h, uint32_t& m) {
    uint32_t t;
    asm("cvt.rn.bf16x2.f32 %0, %1, %2;" : "=r"(t) : "f"(b), "f"(a));
    float fa = __uint_as_float(t << 16);
    float fb = __uint_as_float(t & 0xffff0000u);
    float ra = a - fa, rb = b - fb;
    h = t;
    asm("cvt.rn.bf16x2.f32 %0, %1, %2;" : "=r"(t) : "f"(rb), "f"(ra));
    m = t;
}

__device__ __forceinline__ void cp16(uint32_t dst, const void* src) {
    asm volatile("cp.async.cg.shared.global [%0], [%1], 16;" :: "r"(dst), "l"(src));
}
// zero-fill variant: src_size = 0 -> smem gets zeros (no gmem read)
__device__ __forceinline__ void cp16z(uint32_t dst, const void* src, int valid) {
    int sz = valid ? 16 : 0;
    asm volatile("cp.async.cg.shared.global [%0], [%1], 16, %2;"
                 :: "r"(dst), "l"(src), "r"(sz));
}
#define CP_COMMIT() asm volatile("cp.async.commit_group;" ::: "memory")
#define CP_WAIT1()  asm volatile("cp.async.wait_group 1;"  ::: "memory")

__device__ __forceinline__ void ldsm4(uint32_t* d, uint32_t addr) {
    asm volatile("ldmatrix.sync.aligned.m8n8.x4.shared.b16 {%0,%1,%2,%3}, [%4];"
                 : "=r"(d[0]), "=r"(d[1]), "=r"(d[2]), "=r"(d[3]) : "r"(addr));
}

__device__ __forceinline__ void mma16816(float* c, const uint32_t* a,
                                         uint32_t b0, uint32_t b1) {
    asm volatile(
        "mma.sync.aligned.m16n8k16.row.col.f32.bf16.bf16.f32 "
        "{%0,%1,%2,%3}, {%4,%5,%6,%7}, {%8,%9}, {%0,%1,%2,%3};"
        : "+f"(c[0]), "+f"(c[1]), "+f"(c[2]), "+f"(c[3])
        : "r"(a[0]), "r"(a[1]), "r"(a[2]), "r"(a[3]), "r"(b0), "r"(b1));
}

// ---------------------------------------------------------------------------
// GEMM + inline fp32->bf16x2 split + fused layer-1 LIF scan.
// BM=128 BN=128 BK=32, 256 threads (8 warps, 64x32 warp tiles), 3-stage
// cp.async pipeline of fp32 tiles, in-place conversion to hi/mid bf16
// (fp32 stage = 32 KB = exactly the hi+mid bf16 stage), 2 CTAs/SM.
//
// Stage layout (32 KB), during load:
//   fp32 A [0,16K): 128 rows x 128 B ; fp32 B [16K,32K)
// after in-place convert:
//   Ahi [0,8K) Amid [8K,16K) Bhi [16K,24K) Bmid [24K,32K), 64-B swizzled rows
// ---------------------------------------------------------------------------
#define BM 128
#define BN 128
#define BK 32
#define STAGES 3
#define KTILES (K_DIM / BK)        // 200
#define SPLIT_SM 8192              // 128 rows x 64 B
#define STAGE_SM (4 * SPLIT_SM)    // 32768 B
#define GEMM_SMEM (STAGES * STAGE_SM)  // 98304 B

#define HS 132                     // h1 smem row stride (floats)

#define SWZ(r, c) (((r) << 6) + (((c) ^ (((r) >> 1) & 3)) << 4))

__global__ __launch_bounds__(256, 2)
void gemm_scan_fused(const float* __restrict__ X,
                     const float* __restrict__ W1,
                     const float* __restrict__ bias)
{
    extern __shared__ char smem[];
    const uint32_t smb = smem_to_u32(smem);
    const int tid  = threadIdx.x;
    const int wid  = tid >> 5;
    const int lane = tid & 31;
    const int bm = blockIdx.y * BM;
    const int bn = blockIdx.x * BN;
    const int warp_m = (wid >> 2) * 64;
    const int warp_n = (wid & 3) * 32;

    // ---- fp32 cp.async plan: 8 chunks of 16B per thread per stage ----
    // thread covers rows r0 + j*32 (j=0..3), chunk c0, of A and B fp32 tiles
    const int r0 = tid >> 3;             // 0..31
    const int c0 = tid & 7;              // 0..7
    const float* pA = X  + (size_t)(bm + r0) * K_DIM + c0 * 4;
    const float* pB = W1 + (size_t)(bn + r0) * K_DIM + c0 * 4;
    const uint32_t soA = (uint32_t)(r0 * 128 + c0 * 16);
    const uint32_t soB = 16384u + soA;
    int validB[4];
#pragma unroll
    for (int j = 0; j < 4; ++j) validB[j] = (bn + r0 + j * 32) < N_DIM;
    const size_t JROW = (size_t)32 * K_DIM;     // +32 rows in gmem (floats)

#define ISSUE_STAGE(stb_) do {                                            \
        cp16((stb_) + soA,         pA);                                   \
        cp16((stb_) + soA + 4096,  pA + JROW);                            \
        cp16((stb_) + soA + 8192,  pA + 2 * JROW);                        \
        cp16((stb_) + soA + 12288, pA + 3 * JROW);                        \
        cp16z((stb_) + soB,         validB[0] ? pB            : W1, validB[0]); \
        cp16z((stb_) + soB + 4096,  validB[1] ? pB +     JROW : W1, validB[1]); \
        cp16z((stb_) + soB + 8192,  validB[2] ? pB + 2 * JROW : W1, validB[2]); \
        cp16z((stb_) + soB + 12288, validB[3] ? pB + 3 * JROW : W1, validB[3]); \
        pA += BK; pB += BK;                                               \
    } while (0)

    float acc[4][4][4];
#pragma unroll
    for (int mt = 0; mt < 4; ++mt)
#pragma unroll
        for (int nt = 0; nt < 4; ++nt)
#pragma unroll
            for (int e = 0; e < 4; ++e) acc[mt][nt][e] = 0.0f;

    // prologue: prefetch stages 0,1 (fp32)
#pragma unroll
    for (int s = 0; s < STAGES - 1; ++s) {
        ISSUE_STAGE(smb + s * STAGE_SM);
        CP_COMMIT();
    }

    const int lr  = lane & 15;
    const int lch = lane >> 4;
    const int crow = tid >> 1;      // conversion mapping
    const int chv  = tid & 1;

    int bc = 0;
    int bp = STAGES - 1;

    for (int kt = 0; kt < KTILES; ++kt) {
        CP_WAIT1();
        __syncthreads();            // stage bc fp32 fully visible

        // ---- in-place convert stage bc: fp32 -> bf16 hi/mid ----
        {
            char* sb = smem + bc * STAGE_SM;
            const char* rb = sb + crow * 128 + chv * 64;
            const float4 va0 = *(const float4*)(rb + 0);
            const float4 va1 = *(const float4*)(rb + 16);
            const float4 va2 = *(const float4*)(rb + 32);
            const float4 va3 = *(const float4*)(rb + 48);
            const float4 vb0 = *(const float4*)(rb + 16384 + 0);
            const float4 vb1 = *(const float4*)(rb + 16384 + 16);
            const float4 vb2 = *(const float4*)(rb + 16384 + 32);
            const float4 vb3 = *(const float4*)(rb + 16384 + 48);
            __syncthreads();        // all reads done before any write

            const uint32_t sw0 = SWZ(crow, chv * 2);
            const uint32_t sw1 = SWZ(crow, chv * 2 + 1);
            uint32_t h[8], m[8];
            split2(va0.x, va0.y, h[0], m[0]); split2(va0.z, va0.w, h[1], m[1]);
            split2(va1.x, va1.y, h[2], m[2]); split2(va1.z, va1.w, h[3], m[3]);
            split2(va2.x, va2.y, h[4], m[4]); split2(va2.z, va2.w, h[5], m[5]);
            split2(va3.x, va3.y, h[6], m[6]); split2(va3.z, va3.w, h[7], m[7]);
            *(uint4*)(sb + sw0)        = make_uint4(h[0], h[1], h[2], h[3]);
            *(uint4*)(sb + sw1)        = make_uint4(h[4], h[5], h[6], h[7]);
            *(uint4*)(sb + 8192 + sw0) = make_uint4(m[0], m[1], m[2], m[3]);
            *(uint4*)(sb + 8192 + sw1) = make_uint4(m[4], m[5], m[6], m[7]);

            split2(vb0.x, vb0.y, h[0], m[0]); split2(vb0.z, vb0.w, h[1], m[1]);
            split2(vb1.x, vb1.y, h[2], m[2]); split2(vb1.z, vb1.w, h[3], m[3]);
            split2(vb2.x, vb2.y, h[4], m[4]); split2(vb2.z, vb2.w, h[5], m[5]);
            split2(vb3.x, vb3.y, h[6], m[6]); split2(vb3.z, vb3.w, h[7], m[7]);
            *(uint4*)(sb + 16384 + sw0) = make_uint4(h[0], h[1], h[2], h[3]);
            *(uint4*)(sb + 16384 + sw1) = make_uint4(h[4], h[5], h[6], h[7]);
            *(uint4*)(sb + 24576 + sw0) = make_uint4(m[0], m[1], m[2], m[3]);
            *(uint4*)(sb + 24576 + sw1) = make_uint4(m[4], m[5], m[6], m[7]);
        }

        // issue fp32 prefetch for stage kt+2 (into retired buffer)
        if (kt + STAGES - 1 < KTILES) {
            ISSUE_STAGE(smb + bp * STAGE_SM);
        }
        CP_COMMIT();
        __syncthreads();            // bf16 writes visible to ldsm

        const uint32_t stb = smb + bc * STAGE_SM;

#pragma unroll
        for (int k16 = 0; k16 < 2; ++k16) {
            const int c = k16 * 2 + lch;

            uint32_t af[4][4];       // reused: A-hi then A-mid
            uint32_t bh[2][4];
            uint32_t bmf[2][4];

#pragma unroll
            for (int mt = 0; mt < 4; ++mt)
                ldsm4(af[mt], stb + 0 * SPLIT_SM + SWZ(warp_m + mt * 16 + lr, c));
#pragma unroll
            for (int np = 0; np < 2; ++np)
                ldsm4(bh[np],  stb + 2 * SPLIT_SM + SWZ(warp_n + np * 16 + lr, c));
#pragma unroll
            for (int np = 0; np < 2; ++np)
                ldsm4(bmf[np], stb + 3 * SPLIT_SM + SWZ(warp_n + np * 16 + lr, c));

            // pass hh
#pragma unroll
            for (int mt = 0; mt < 4; ++mt)
#pragma unroll
                for (int nt = 0; nt < 4; ++nt) {
                    const int np = nt >> 1, sel = nt & 1;
                    mma16816(acc[mt][nt], af[mt], bh[np][sel], bh[np][sel + 2]);
                }
            // pass hm
#pragma unroll
            for (int mt = 0; mt < 4; ++mt)
#pragma unroll
                for (int nt = 0; nt < 4; ++nt) {
                    const int np = nt >> 1, sel = nt & 1;
                    mma16816(acc[mt][nt], af[mt], bmf[np][sel], bmf[np][sel + 2]);
                }
            // A-mid overwrites af
#pragma unroll
            for (int mt = 0; mt < 4; ++mt)
                ldsm4(af[mt], stb + 1 * SPLIT_SM + SWZ(warp_m + mt * 16 + lr, c));
            // pass mh
#pragma unroll
            for (int mt = 0; mt < 4; ++mt)
#pragma unroll
                for (int nt = 0; nt < 4; ++nt) {
                    const int np = nt >> 1, sel = nt & 1;
                    mma16816(acc[mt][nt], af[mt], bh[np][sel], bh[np][sel + 2]);
                }
        }

        bc = (bc == STAGES - 1) ? 0 : bc + 1;
        bp = (bp == STAGES - 1) ? 0 : bp + 1;
    }

    // ---- epilogue 1: acc (+bias) -> smem h1 tile [128 m][HS] ----
    __syncthreads();
    float* smh1 = (float*)smem;

    const int lrow = lane >> 2;
    const int lcol = (lane & 3) * 2;
#pragma unroll
    for (int nt = 0; nt < 4; ++nt) {
        const int nl = warp_n + nt * 8 + lcol;
        const int ng = bn + nl;
        const float bx = (ng < N_DIM)     ? bias[ng]     : 0.0f;
        const float by = (ng + 1 < N_DIM) ? bias[ng + 1] : 0.0f;
#pragma unroll
        for (int mt = 0; mt < 4; ++mt) {
            const int m0 = warp_m + mt * 16 + lrow;
            smh1[(size_t)m0 * HS + nl]           = acc[mt][nt][0] + bx;
            smh1[(size_t)m0 * HS + nl + 1]       = acc[mt][nt][1] + by;
            smh1[(size_t)(m0 + 8) * HS + nl]     = acc[mt][nt][2] + bx;
            smh1[(size_t)(m0 + 8) * HS + nl + 1] = acc[mt][nt][3] + by;
        }
    }
    __syncthreads();

    // ---- epilogue 2: fused LIF scan over the 4 batches in this tile ----
    {
        const int hl    = tid & 127;
        const int half  = tid >> 7;
        const int hg    = bn + hl;
        const bool valid = (hg < N_DIM);
        const int b0    = (bm >> 5);

#pragma unroll
        for (int q = 0; q < 2; ++q) {
            const int bq = half * 2 + q;
            const int b  = b0 + bq;
            float mem = 0.0f;
            int flg = 0;
#pragma unroll 4
            for (int t = 0; t < TSTEPS; ++t) {
                const float cur = valid ? smh1[(size_t)(bq * 32 + t) * HS + hl] : 0.0f;
                const float mn  = (mem > THR_F) ? 0.0f : fmaf(BETA_F, mem, cur);
                mem = mn;
                const bool spk = valid && (mn > THR_F);
                if (valid && fabsf(mn - THR_F) < TOL_F) flg = 1;
                const uint32_t bits = __ballot_sync(0xffffffffu, spk);
                if (lane == 0)
                    g_spk1[(size_t)(b * TSTEPS + t) * 32 + (hg >> 5)] = bits;
            }
            if (flg) {
                const int i = atomicAdd(&g_nflag, 1);
                if (i < FLAG_CAP) g_flag[i] = (b << 10) | hg;
            }
        }
    }
#undef ISSUE_STAGE
}

// ---------------------------------------------------------------------------
// Fixup: one CTA per flagged (b,h) entry (grid-stride), 512 threads.
// 16 warps x 2 timesteps; k-loop unrolled x2. Dots -> smem; thread 0 runs
// the 32-step recurrence and patches spk1 bits.
// ---------------------------------------------------------------------------
__global__ __launch_bounds__(512)
void snn_fixup_kernel(const float* __restrict__ X,
                      const float* __restrict__ W1,
                      const float* __restrict__ b1)
{
    __shared__ float sdot[TSTEPS];

    const int tid  = threadIdx.x;
    const int lane = tid & 31;
    const int warp = tid >> 5;          // 0..15
    int total = g_nflag;
    if (total > FLAG_CAP) total = FLAG_CAP;

    for (int e = blockIdx.x; e < total; e += gridDim.x) {
        const int pair = g_flag[e];
        const int b = pair >> 10;
        const int h = pair & 1023;
        const float* wrow = W1 + (size_t)h * K_DIM;

        const int t0 = warp * 2;
        const float* xr0 = X + (size_t)(b * TSTEPS + t0 + 0) * K_DIM;
        const float* xr1 = X + (size_t)(b * TSTEPS + t0 + 1) * K_DIM;

        float s0 = 0.f, s1 = 0.f;
#pragma unroll 2
        for (int k = lane * 4; k < K_DIM; k += 128) {
            const float4 wv = *(const float4*)(wrow + k);
            const float4 x0 = *(const float4*)(xr0 + k);
            const float4 x1 = *(const float4*)(xr1 + k);
            s0 = fmaf(x0.x, wv.x, s0); s0 = fmaf(x0.y, wv.y, s0);
            s0 = fmaf(x0.z, wv.z, s0); s0 = fmaf(x0.w, wv.w, s0);
            s1 = fmaf(x1.x, wv.x, s1); s1 = fmaf(x1.y, wv.y, s1);
            s1 = fmaf(x1.z, wv.z, s1); s1 = fmaf(x1.w, wv.w, s1);
        }
#pragma unroll
        for (int o = 16; o; o >>= 1) {
            s0 += __shfl_xor_sync(0xffffffffu, s0, o);
            s1 += __shfl_xor_sync(0xffffffffu, s1, o);
        }
        if (lane == 0) {
            sdot[t0 + 0] = s0;
            sdot[t0 + 1] = s1;
        }
        __syncthreads();

        if (tid == 0) {
            const float bv = b1[h];
            const uint32_t bit = 1u << (h & 31);
            float mem = 0.0f;
            for (int t = 0; t < TSTEPS; t++) {
                const float cur = sdot[t] + bv;
                const float mn  = (mem > THR_F) ? 0.0f : fmaf(BETA_F, mem, cur);
                mem = mn;
                uint32_t* wptr = &g_spk1[(size_t)(b * TSTEPS + t) * 32 + (h >> 5)];
                if (mn > THR_F) atomicOr(wptr, bit);
                else            atomicAnd(wptr, ~bit);
            }
        }
        __syncthreads();
    }
}

// ---------------------------------------------------------------------------
// Layer-2 (t-parallel): spk1 bits + W2 staged to smem, 8 warps x 4 timesteps
// compute h2 dots; thread 0 runs the LIF scan. Also resets g_nflag for the
// next invocation (fixup has already consumed it).
// ---------------------------------------------------------------------------
__global__ __launch_bounds__(256)
void snn_layer2_kernel(const float* __restrict__ W2,
                       const float* __restrict__ b2,
                       float* __restrict__ out)
{
    __shared__ float    sW2[ACT][HID];
    __shared__ uint32_t sbits[TSTEPS][32];
    __shared__ float    sdot[TSTEPS][ACT];

    const int b    = blockIdx.x;
    const int tid  = threadIdx.x;
    const int lane = tid & 31;
    const int warp = tid >> 5;          // 0..7

    if (b == 0 && tid == 0) g_nflag = 0;   // reset for next launch (post-fixup)

    for (int i = tid; i < ACT * HID; i += 256)
        sW2[i / HID][i % HID] = W2[i];
    for (int i = tid; i < TSTEPS * 32; i += 256)
        sbits[i >> 5][i & 31] = g_spk1[(size_t)(b * TSTEPS + (i >> 5)) * 32 + (i & 31)];
    __syncthreads();

#pragma unroll
    for (int q = 0; q < 4; ++q) {
        const int t = warp * 4 + q;
        float a0 = 0.f, a1 = 0.f, a2 = 0.f, a3 = 0.f;
#pragma unroll 4
        for (int j = 0; j < 32; ++j) {
            const int h = j * 32 + lane;
            if (h < HID && ((sbits[t][j] >> lane) & 1u)) {
                a0 += sW2[0][h]; a1 += sW2[1][h];
                a2 += sW2[2][h]; a3 += sW2[3][h];
            }
        }
#pragma unroll
        for (int o = 16; o; o >>= 1) {
            a0 += __shfl_xor_sync(0xffffffffu, a0, o);
            a1 += __shfl_xor_sync(0xffffffffu, a1, o);
            a2 += __shfl_xor_sync(0xffffffffu, a2, o);
            a3 += __shfl_xor_sync(0xffffffffu, a3, o);
        }
        if (lane == 0) {
            sdot[t][0] = a0; sdot[t][1] = a1;
            sdot[t][2] = a2; sdot[t][3] = a3;
        }
    }
    __syncthreads();

    if (tid == 0) {
        float m2[ACT] = {0.f, 0.f, 0.f, 0.f};
        for (int t = 0; t < TSTEPS; t++) {
#pragma unroll
            for (int a = 0; a < ACT; a++) {
                const float h2 = sdot[t][a] + b2[a];
                const float mn = (m2[a] > THR_F) ? 0.0f : fmaf(BETA_F, m2[a], h2);
                m2[a] = mn;
                out[((size_t)(b * TSTEPS + t)) * ACT + a] = (mn > THR_F) ? 1.0f : 0.0f;
            }
        }
    }
}

// ---------------------------------------------------------------------------
extern "C" void kernel_launch(void* const* d_in, const int* in_sizes, int n_in,
                              void* d_out, int out_size)
{
    const float* x  = (const float*)d_in[0];   // [128,32,6400]
    const float* W1 = (const float*)d_in[1];   // [1000,6400]
    const float* b1 = (const float*)d_in[2];   // [1000]
    const float* W2 = (const float*)d_in[3];   // [4,1000]
    const float* b2 = (const float*)d_in[4];   // [4]
    float* out = (float*)d_out;                // [128,32,4]

    cudaFuncSetAttribute(gemm_scan_fused,
                         cudaFuncAttributeMaxDynamicSharedMemorySize, GEMM_SMEM);

    dim3 grid(N_PAD / BN, M_DIM / BM);         // (8, 32)
    gemm_scan_fused<<<grid, 256, GEMM_SMEM>>>(x, W1, b1);

    snn_fixup_kernel<<<512, 512>>>(x, W1, b1);
    snn_layer2_kernel<<<BATCH, 256>>>(W2, b2, out);
}

// round 13
// speedup vs baseline: 1.2783x; 1.2783x over previous
#include <cuda_runtime.h>
#include <cuda_bf16.h>
#include <cstdint>

// ---------------------------------------------------------------------------
// Problem dims
// ---------------------------------------------------------------------------
#define BATCH   128
#define TSTEPS  32
#define D_DIM   6400
#define HID     1000
#define ACT     4
#define M_DIM   (BATCH * TSTEPS)   // 4096
#define N_DIM   HID                // 1000
#define N_PAD   1024
#define K_DIM   D_DIM              // 6400

#define BETA_F  0.99f
#define THR_F   1.0f
#define TOL_F   2.5e-4f            // borderline margin -> exact fp32 recompute
#define FLAG_CAP 65536

// ---------------------------------------------------------------------------
// Global scratch
// ---------------------------------------------------------------------------
__device__ __nv_bfloat16 g_Ah[M_DIM * K_DIM];             // 52.4 MB each
__device__ __nv_bfloat16 g_Am[M_DIM * K_DIM];
__device__ __nv_bfloat16 g_Bh[N_PAD * K_DIM];             // 13.1 MB each
__device__ __nv_bfloat16 g_Bm[N_PAD * K_DIM];

__device__ uint32_t g_spk1[M_DIM * 32];                   // bit-packed spk1
__device__ int      g_nflag;
__device__ int      g_flag[FLAG_CAP];                     // packed (b<<10)|h

// ---------------------------------------------------------------------------
// Helpers
// ---------------------------------------------------------------------------
__device__ __forceinline__ uint32_t smem_to_u32(const void* p) {
    uint32_t a;
    asm("{ .reg .u64 t; cvta.to.shared.u64 t, %1; cvt.u32.u64 %0, t; }" : "=r"(a) : "l"(p));
    return a;
}

// 2-way bf16 split of two fp32 values packed as bf16x2 (lo = elem a, hi = elem b).
__device__ __forceinline__ void split2(float a, float b, uint32_t& h, uint32_t& m) {
    uint32_t t;
    asm("cvt.rn.bf16x2.f32 %0, %1, %2;" : "=r"(t) : "f"(b), "f"(a));
    float fa = __uint_as_float(t << 16);
    float fb = __uint_as_float(t & 0xffff0000u);
    float ra = a - fa, rb = b - fb;
    h = t;
    asm("cvt.rn.bf16x2.f32 %0, %1, %2;" : "=r"(t) : "f"(rb), "f"(ra));
    m = t;
}

__device__ __forceinline__ void cp16(uint32_t dst, const void* src) {
    asm volatile("cp.async.cg.shared.global [%0], [%1], 16;" :: "r"(dst), "l"(src));
}
#define CP_COMMIT() asm volatile("cp.async.commit_group;" ::: "memory")
#define CP_WAIT1()  asm volatile("cp.async.wait_group 1;"  ::: "memory")

__device__ __forceinline__ void ldsm4(uint32_t* d, uint32_t addr) {
    asm volatile("ldmatrix.sync.aligned.m8n8.x4.shared.b16 {%0,%1,%2,%3}, [%4];"
                 : "=r"(d[0]), "=r"(d[1]), "=r"(d[2]), "=r"(d[3]) : "r"(addr));
}

__device__ __forceinline__ void mma16816(float* c, const uint32_t* a,
                                         uint32_t b0, uint32_t b1) {
    asm volatile(
        "mma.sync.aligned.m16n8k16.row.col.f32.bf16.bf16.f32 "
        "{%0,%1,%2,%3}, {%4,%5,%6,%7}, {%8,%9}, {%0,%1,%2,%3};"
        : "+f"(c[0]), "+f"(c[1]), "+f"(c[2]), "+f"(c[3])
        : "r"(a[0]), "r"(a[1]), "r"(a[2]), "r"(a[3]), "r"(b0), "r"(b1));
}

// ---------------------------------------------------------------------------
// Single split kernel: fp32 -> (hi, mid) bf16 for both X and W1.
// Word index space: [0, XW) -> X ; [XW, XW+WW) -> W1 (padded rows zeroed).
// ---------------------------------------------------------------------------
#define XWORDS (M_DIM * K_DIM / 2)     // 13,107,200
#define WWORDS (N_PAD * K_DIM / 2)     //  3,276,800

__global__ __launch_bounds__(256)
void split_kernel(const float* __restrict__ X, const float* __restrict__ W1)
{
    if (blockIdx.x == 0 && threadIdx.x == 0) g_nflag = 0;
    const size_t w = (size_t)blockIdx.x * 256 + threadIdx.x;
    if (w < XWORDS) {
        const float2 v = ((const float2*)X)[w];
        uint32_t h, m;
        split2(v.x, v.y, h, m);
        ((uint32_t*)g_Ah)[w] = h;
        ((uint32_t*)g_Am)[w] = m;
    } else if (w < XWORDS + WWORDS) {
        const size_t ww = w - XWORDS;
        const size_t row = (ww * 2) / K_DIM;
        uint32_t h = 0, m = 0;
        if (row < N_DIM) {
            const float2 v = ((const float2*)W1)[ww];
            split2(v.x, v.y, h, m);
        }
        ((uint32_t*)g_Bh)[ww] = h;
        ((uint32_t*)g_Bm)[ww] = m;
    }
}

// ---------------------------------------------------------------------------
// GEMM + fused layer-1 LIF scan (R10 structure — 1 sync per k-tile).
// BM=128 BN=128 BK=32, 256 threads (8 warps, 64x32 warp tiles), 3-stage
// cp.async pipeline, 2 CTAs/SM, pass-sequenced fragments (hh -> hm -> mh).
// ---------------------------------------------------------------------------
#define BM 128
#define BN 128
#define BK 32
#define STAGES 3
#define KTILES (K_DIM / BK)        // 200
#define SPLIT_SM 8192              // 128 rows x 64 B
#define STAGE_SM (4 * SPLIT_SM)    // 32768 B
#define GEMM_SMEM (STAGES * STAGE_SM)  // 98304 B

#define HS 132                     // h1 smem row stride (floats)

#define SWZ(r, c) (((r) << 6) + (((c) ^ (((r) >> 1) & 3)) << 4))

__global__ __launch_bounds__(256, 2)
void gemm_scan_fused(const float* __restrict__ bias)
{
    extern __shared__ char smem[];
    const uint32_t smb = smem_to_u32(smem);
    const int tid  = threadIdx.x;
    const int wid  = tid >> 5;
    const int lane = tid & 31;
    const int bm = blockIdx.y * BM;
    const int bn = blockIdx.x * BN;
    const int warp_m = (wid >> 2) * 64;
    const int warp_n = (wid & 3) * 32;

    // Compact load plan: 4 running pointers + 4 smem offsets.
    const int r0 = tid >> 2;             // 0..63
    const int cc = tid & 3;
    const __nv_bfloat16* gp0 = g_Ah + (size_t)(bm + r0) * K_DIM + cc * 8;
    const __nv_bfloat16* gp1 = g_Am + (size_t)(bm + r0) * K_DIM + cc * 8;
    const __nv_bfloat16* gp2 = g_Bh + (size_t)(bn + r0) * K_DIM + cc * 8;
    const __nv_bfloat16* gp3 = g_Bm + (size_t)(bn + r0) * K_DIM + cc * 8;
    const uint32_t sw = SWZ(r0, cc);     // SWZ(r0+64,cc) = sw + 4096
    const uint32_t so0 = 0 * SPLIT_SM + sw;
    const uint32_t so1 = 1 * SPLIT_SM + sw;
    const uint32_t so2 = 2 * SPLIT_SM + sw;
    const uint32_t so3 = 3 * SPLIT_SM + sw;
    const size_t ROWOFF = (size_t)64 * K_DIM;   // +64 rows in gmem

#define ISSUE_STAGE(stb) do {                                  \
        cp16((stb) + so0,        gp0);                         \
        cp16((stb) + so0 + 4096, gp0 + ROWOFF);                \
        cp16((stb) + so1,        gp1);                         \
        cp16((stb) + so1 + 4096, gp1 + ROWOFF);                \
        cp16((stb) + so2,        gp2);                         \
        cp16((stb) + so2 + 4096, gp2 + ROWOFF);                \
        cp16((stb) + so3,        gp3);                         \
        cp16((stb) + so3 + 4096, gp3 + ROWOFF);                \
        gp0 += BK; gp1 += BK; gp2 += BK; gp3 += BK;            \
    } while (0)

    float acc[4][4][4];
#pragma unroll
    for (int mt = 0; mt < 4; ++mt)
#pragma unroll
        for (int nt = 0; nt < 4; ++nt)
#pragma unroll
            for (int e = 0; e < 4; ++e) acc[mt][nt][e] = 0.0f;

    // prologue: prefetch stages 0,1
#pragma unroll
    for (int s = 0; s < STAGES - 1; ++s) {
        ISSUE_STAGE(smb + s * STAGE_SM);
        CP_COMMIT();
    }

    const int lr  = lane & 15;
    const int lch = lane >> 4;

    int bc = 0;
    int bp = STAGES - 1;

    for (int kt = 0; kt < KTILES; ++kt) {
        CP_WAIT1();
        __syncthreads();

        if (kt + STAGES - 1 < KTILES) {
            ISSUE_STAGE(smb + bp * STAGE_SM);
        }
        CP_COMMIT();

        const uint32_t stb = smb + bc * STAGE_SM;

#pragma unroll
        for (int k16 = 0; k16 < 2; ++k16) {
            const int c = k16 * 2 + lch;

            uint32_t af[4][4];       // reused: A-hi then A-mid
            uint32_t bh[2][4];
            uint32_t bmf[2][4];

#pragma unroll
            for (int mt = 0; mt < 4; ++mt)
                ldsm4(af[mt], stb + 0 * SPLIT_SM + SWZ(warp_m + mt * 16 + lr, c));
#pragma unroll
            for (int np = 0; np < 2; ++np)
                ldsm4(bh[np],  stb + 2 * SPLIT_SM + SWZ(warp_n + np * 16 + lr, c));
#pragma unroll
            for (int np = 0; np < 2; ++np)
                ldsm4(bmf[np], stb + 3 * SPLIT_SM + SWZ(warp_n + np * 16 + lr, c));

            // pass hh
#pragma unroll
            for (int mt = 0; mt < 4; ++mt)
#pragma unroll
                for (int nt = 0; nt < 4; ++nt) {
                    const int np = nt >> 1, sel = nt & 1;
                    mma16816(acc[mt][nt], af[mt], bh[np][sel], bh[np][sel + 2]);
                }
            // pass hm
#pragma unroll
            for (int mt = 0; mt < 4; ++mt)
#pragma unroll
                for (int nt = 0; nt < 4; ++nt) {
                    const int np = nt >> 1, sel = nt & 1;
                    mma16816(acc[mt][nt], af[mt], bmf[np][sel], bmf[np][sel + 2]);
                }
            // A-mid overwrites af (WAR caps fragment liveness)
#pragma unroll
            for (int mt = 0; mt < 4; ++mt)
                ldsm4(af[mt], stb + 1 * SPLIT_SM + SWZ(warp_m + mt * 16 + lr, c));
            // pass mh
#pragma unroll
            for (int mt = 0; mt < 4; ++mt)
#pragma unroll
                for (int nt = 0; nt < 4; ++nt) {
                    const int np = nt >> 1, sel = nt & 1;
                    mma16816(acc[mt][nt], af[mt], bh[np][sel], bh[np][sel + 2]);
                }
        }

        bc = (bc == STAGES - 1) ? 0 : bc + 1;
        bp = (bp == STAGES - 1) ? 0 : bp + 1;
    }

    // ---- epilogue 1: acc (+bias) -> smem h1 tile [128 m][HS] ----
    __syncthreads();
    float* smh1 = (float*)smem;

    const int lrow = lane >> 2;
    const int lcol = (lane & 3) * 2;
#pragma unroll
    for (int nt = 0; nt < 4; ++nt) {
        const int nl = warp_n + nt * 8 + lcol;
        const int ng = bn + nl;
        const float bx = (ng < N_DIM)     ? bias[ng]     : 0.0f;
        const float by = (ng + 1 < N_DIM) ? bias[ng + 1] : 0.0f;
#pragma unroll
        for (int mt = 0; mt < 4; ++mt) {
            const int m0 = warp_m + mt * 16 + lrow;
            smh1[(size_t)m0 * HS + nl]           = acc[mt][nt][0] + bx;
            smh1[(size_t)m0 * HS + nl + 1]       = acc[mt][nt][1] + by;
            smh1[(size_t)(m0 + 8) * HS + nl]     = acc[mt][nt][2] + bx;
            smh1[(size_t)(m0 + 8) * HS + nl + 1] = acc[mt][nt][3] + by;
        }
    }
    __syncthreads();

    // ---- epilogue 2: fused LIF scan over the 4 batches in this tile ----
    {
        const int hl    = tid & 127;
        const int half  = tid >> 7;
        const int hg    = bn + hl;
        const bool valid = (hg < N_DIM);
        const int b0    = (bm >> 5);

#pragma unroll
        for (int q = 0; q < 2; ++q) {
            const int bq = half * 2 + q;
            const int b  = b0 + bq;
            float mem = 0.0f;
            int flg = 0;
#pragma unroll 4
            for (int t = 0; t < TSTEPS; ++t) {
                const float cur = valid ? smh1[(size_t)(bq * 32 + t) * HS + hl] : 0.0f;
                const float mn  = (mem > THR_F) ? 0.0f : fmaf(BETA_F, mem, cur);
                mem = mn;
                const bool spk = valid && (mn > THR_F);
                if (valid && fabsf(mn - THR_F) < TOL_F) flg = 1;
                const uint32_t bits = __ballot_sync(0xffffffffu, spk);
                if (lane == 0)
                    g_spk1[(size_t)(b * TSTEPS + t) * 32 + (hg >> 5)] = bits;
            }
            if (flg) {
                const int i = atomicAdd(&g_nflag, 1);
                if (i < FLAG_CAP) g_flag[i] = (b << 10) | hg;
            }
        }
    }
#undef ISSUE_STAGE
}

// ---------------------------------------------------------------------------
// Fixup: one CTA per flagged (b,h) entry (grid-stride), 512 threads.
// 16 warps x 2 timesteps; k-loop unrolled x2. Dots -> smem; thread 0 runs
// the 32-step recurrence and patches spk1 bits.
// ---------------------------------------------------------------------------
__global__ __launch_bounds__(512)
void snn_fixup_kernel(const float* __restrict__ X,
                      const float* __restrict__ W1,
                      const float* __restrict__ b1)
{
    __shared__ float sdot[TSTEPS];

    const int tid  = threadIdx.x;
    const int lane = tid & 31;
    const int warp = tid >> 5;          // 0..15
    int total = g_nflag;
    if (total > FLAG_CAP) total = FLAG_CAP;

    for (int e = blockIdx.x; e < total; e += gridDim.x) {
        const int pair = g_flag[e];
        const int b = pair >> 10;
        const int h = pair & 1023;
        const float* wrow = W1 + (size_t)h * K_DIM;

        const int t0 = warp * 2;
        const float* xr0 = X + (size_t)(b * TSTEPS + t0 + 0) * K_DIM;
        const float* xr1 = X + (size_t)(b * TSTEPS + t0 + 1) * K_DIM;

        float s0 = 0.f, s1 = 0.f;
#pragma unroll 2
        for (int k = lane * 4; k < K_DIM; k += 128) {
            const float4 wv = *(const float4*)(wrow + k);
            const float4 x0 = *(const float4*)(xr0 + k);
            const float4 x1 = *(const float4*)(xr1 + k);
            s0 = fmaf(x0.x, wv.x, s0); s0 = fmaf(x0.y, wv.y, s0);
            s0 = fmaf(x0.z, wv.z, s0); s0 = fmaf(x0.w, wv.w, s0);
            s1 = fmaf(x1.x, wv.x, s1); s1 = fmaf(x1.y, wv.y, s1);
            s1 = fmaf(x1.z, wv.z, s1); s1 = fmaf(x1.w, wv.w, s1);
        }
#pragma unroll
        for (int o = 16; o; o >>= 1) {
            s0 += __shfl_xor_sync(0xffffffffu, s0, o);
            s1 += __shfl_xor_sync(0xffffffffu, s1, o);
        }
        if (lane == 0) {
            sdot[t0 + 0] = s0;
            sdot[t0 + 1] = s1;
        }
        __syncthreads();

        if (tid == 0) {
            const float bv = b1[h];
            const uint32_t bit = 1u << (h & 31);
            float mem = 0.0f;
            for (int t = 0; t < TSTEPS; t++) {
                const float cur = sdot[t] + bv;
                const float mn  = (mem > THR_F) ? 0.0f : fmaf(BETA_F, mem, cur);
                mem = mn;
                uint32_t* wptr = &g_spk1[(size_t)(b * TSTEPS + t) * 32 + (h >> 5)];
                if (mn > THR_F) atomicOr(wptr, bit);
                else            atomicAnd(wptr, ~bit);
            }
        }
        __syncthreads();
    }
}

// ---------------------------------------------------------------------------
// Layer-2 (t-parallel): spk1 bits + W2 staged to smem, 8 warps x 4 timesteps
// compute h2 dots (bit-test); thread 0 runs the LIF scan.
// ---------------------------------------------------------------------------
__global__ __launch_bounds__(256)
void snn_layer2_kernel(const float* __restrict__ W2,
                       const float* __restrict__ b2,
                       float* __restrict__ out)
{
    __shared__ float    sW2[ACT][HID];
    __shared__ uint32_t sbits[TSTEPS][32];
    __shared__ float    sdot[TSTEPS][ACT];

    const int b    = blockIdx.x;
    const int tid  = threadIdx.x;
    const int lane = tid & 31;
    const int warp = tid >> 5;          // 0..7

    for (int i = tid; i < ACT * HID; i += 256)
        sW2[i / HID][i % HID] = W2[i];
    for (int i = tid; i < TSTEPS * 32; i += 256)
        sbits[i >> 5][i & 31] = g_spk1[(size_t)(b * TSTEPS + (i >> 5)) * 32 + (i & 31)];
    __syncthreads();

#pragma unroll
    for (int q = 0; q < 4; ++q) {
        const int t = warp * 4 + q;
        float a0 = 0.f, a1 = 0.f, a2 = 0.f, a3 = 0.f;
#pragma unroll 4
        for (int j = 0; j < 32; ++j) {
            const int h = j * 32 + lane;
            if (h < HID && ((sbits[t][j] >> lane) & 1u)) {
                a0 += sW2[0][h]; a1 += sW2[1][h];
                a2 += sW2[2][h]; a3 += sW2[3][h];
            }
        }
#pragma unroll
        for (int o = 16; o; o >>= 1) {
            a0 += __shfl_xor_sync(0xffffffffu, a0, o);
            a1 += __shfl_xor_sync(0xffffffffu, a1, o);
            a2 += __shfl_xor_sync(0xffffffffu, a2, o);
            a3 += __shfl_xor_sync(0xffffffffu, a3, o);
        }
        if (lane == 0) {
            sdot[t][0] = a0; sdot[t][1] = a1;
            sdot[t][2] = a2; sdot[t][3] = a3;
        }
    }
    __syncthreads();

    if (tid == 0) {
        float m2[ACT] = {0.f, 0.f, 0.f, 0.f};
        for (int t = 0; t < TSTEPS; t++) {
#pragma unroll
            for (int a = 0; a < ACT; a++) {
                const float h2 = sdot[t][a] + b2[a];
                const float mn = (m2[a] > THR_F) ? 0.0f : fmaf(BETA_F, m2[a], h2);
                m2[a] = mn;
                out[((size_t)(b * TSTEPS + t)) * ACT + a] = (mn > THR_F) ? 1.0f : 0.0f;
            }
        }
    }
}

// ---------------------------------------------------------------------------
extern "C" void kernel_launch(void* const* d_in, const int* in_sizes, int n_in,
                              void* d_out, int out_size)
{
    const float* x  = (const float*)d_in[0];   // [128,32,6400]
    const float* W1 = (const float*)d_in[1];   // [1000,6400]
    const float* b1 = (const float*)d_in[2];   // [1000]
    const float* W2 = (const float*)d_in[3];   // [4,1000]
    const float* b2 = (const float*)d_in[4];   // [4]
    float* out = (float*)d_out;                // [128,32,4]

    cudaFuncSetAttribute(gemm_scan_fused,
                         cudaFuncAttributeMaxDynamicSharedMemorySize, GEMM_SMEM);

    {   // single split pass: X then W1 (padded); resets flag counter
        const int nwords = XWORDS + WWORDS;
        split_kernel<<<(nwords + 255) / 256, 256>>>(x, W1);
    }

    dim3 grid(N_PAD / BN, M_DIM / BM);         // (8, 32)
    gemm_scan_fused<<<grid, 256, GEMM_SMEM>>>(b1);

    snn_fixup_kernel<<<512, 512>>>(x, W1, b1);
    snn_layer2_kernel<<<BATCH, 256>>>(W2, b2, out);
}

// round 16
// speedup vs baseline: 1.3579x; 1.0623x over previous
#include <cuda_runtime.h>
#include <cuda_bf16.h>
#include <cstdint>

// ---------------------------------------------------------------------------
// Problem dims
// ---------------------------------------------------------------------------
#define BATCH   128
#define TSTEPS  32
#define D_DIM   6400
#define HID     1000
#define ACT     4
#define M_DIM   (BATCH * TSTEPS)   // 4096
#define N_DIM   HID                // 1000
#define N_PAD   1024
#define K_DIM   D_DIM              // 6400

#define BETA_F  0.99f
#define THR_F   1.0f
#define TOL_F   2.5e-4f            // borderline margin -> exact fp32 recompute
#define FLAG_CAP 65536

// ---------------------------------------------------------------------------
// Global scratch
// ---------------------------------------------------------------------------
__device__ __nv_bfloat16 g_Ah[M_DIM * K_DIM];             // 52.4 MB each
__device__ __nv_bfloat16 g_Am[M_DIM * K_DIM];
__device__ __nv_bfloat16 g_Bh[N_PAD * K_DIM];             // 13.1 MB each
__device__ __nv_bfloat16 g_Bm[N_PAD * K_DIM];

__device__ uint32_t g_spk1[M_DIM * 32];                   // bit-packed spk1
__device__ int      g_nflag;
__device__ int      g_flag[FLAG_CAP];                     // packed (b<<10)|h

// ---------------------------------------------------------------------------
// Helpers
// ---------------------------------------------------------------------------
__device__ __forceinline__ uint32_t smem_to_u32(const void* p) {
    uint32_t a;
    asm("{ .reg .u64 t; cvta.to.shared.u64 t, %1; cvt.u32.u64 %0, t; }" : "=r"(a) : "l"(p));
    return a;
}

// 2-way bf16 split of two fp32 values packed as bf16x2 (lo = elem a, hi = elem b).
__device__ __forceinline__ void split2(float a, float b, uint32_t& h, uint32_t& m) {
    uint32_t t;
    asm("cvt.rn.bf16x2.f32 %0, %1, %2;" : "=r"(t) : "f"(b), "f"(a));
    float fa = __uint_as_float(t << 16);
    float fb = __uint_as_float(t & 0xffff0000u);
    float ra = a - fa, rb = b - fb;
    h = t;
    asm("cvt.rn.bf16x2.f32 %0, %1, %2;" : "=r"(t) : "f"(rb), "f"(ra));
    m = t;
}

__device__ __forceinline__ void cp16(uint32_t dst, const void* src) {
    asm volatile("cp.async.cg.shared.global [%0], [%1], 16;" :: "r"(dst), "l"(src));
}
#define CP_COMMIT() asm volatile("cp.async.commit_group;" ::: "memory")
#define CP_WAIT1()  asm volatile("cp.async.wait_group 1;"  ::: "memory")

__device__ __forceinline__ void ldsm4(uint32_t* d, uint32_t addr) {
    asm volatile("ldmatrix.sync.aligned.m8n8.x4.shared.b16 {%0,%1,%2,%3}, [%4];"
                 : "=r"(d[0]), "=r"(d[1]), "=r"(d[2]), "=r"(d[3]) : "r"(addr));
}

__device__ __forceinline__ void mma16816(float* c, const uint32_t* a,
                                         uint32_t b0, uint32_t b1) {
    asm volatile(
        "mma.sync.aligned.m16n8k16.row.col.f32.bf16.bf16.f32 "
        "{%0,%1,%2,%3}, {%4,%5,%6,%7}, {%8,%9}, {%0,%1,%2,%3};"
        : "+f"(c[0]), "+f"(c[1]), "+f"(c[2]), "+f"(c[3])
        : "r"(a[0]), "r"(a[1]), "r"(a[2]), "r"(a[3]), "r"(b0), "r"(b1));
}

// ---------------------------------------------------------------------------
// Single split kernel (vectorized): fp32 -> (hi, mid) bf16 for X and W1.
// 8 elems per thread: 2x float4 loads, uint4 (16 B) stores.
// ---------------------------------------------------------------------------
#define XGRP (M_DIM * K_DIM / 8)       // 3,276,800 groups of 8 elems
#define WGRP (N_PAD * K_DIM / 8)       //   819,200

__global__ __launch_bounds__(256)
void split_kernel(const float* __restrict__ X, const float* __restrict__ W1)
{
    if (blockIdx.x == 0 && threadIdx.x == 0) g_nflag = 0;
    const size_t g = (size_t)blockIdx.x * 256 + threadIdx.x;
    if (g < XGRP) {
        const float4 v0 = ((const float4*)X)[g * 2];
        const float4 v1 = ((const float4*)X)[g * 2 + 1];
        uint32_t h[4], m[4];
        split2(v0.x, v0.y, h[0], m[0]); split2(v0.z, v0.w, h[1], m[1]);
        split2(v1.x, v1.y, h[2], m[2]); split2(v1.z, v1.w, h[3], m[3]);
        ((uint4*)g_Ah)[g] = make_uint4(h[0], h[1], h[2], h[3]);
        ((uint4*)g_Am)[g] = make_uint4(m[0], m[1], m[2], m[3]);
    } else if (g < XGRP + WGRP) {
        const size_t ww = g - XGRP;
        const size_t row = (ww * 8) / K_DIM;
        uint32_t h[4] = {0, 0, 0, 0}, m[4] = {0, 0, 0, 0};
        if (row < N_DIM) {
            const float4 v0 = ((const float4*)W1)[ww * 2];
            const float4 v1 = ((const float4*)W1)[ww * 2 + 1];
            split2(v0.x, v0.y, h[0], m[0]); split2(v0.z, v0.w, h[1], m[1]);
            split2(v1.x, v1.y, h[2], m[2]); split2(v1.z, v1.w, h[3], m[3]);
        }
        ((uint4*)g_Bh)[ww] = make_uint4(h[0], h[1], h[2], h[3]);
        ((uint4*)g_Bm)[ww] = make_uint4(m[0], m[1], m[2], m[3]);
    }
}

// ---------------------------------------------------------------------------
// GEMM + fused layer-1 LIF scan (unchanged from R13 — proven at ~505 us).
// BM=128 BN=128 BK=32, 256 threads (8 warps, 64x32 warp tiles), 3-stage
// cp.async pipeline, 2 CTAs/SM, pass-sequenced fragments (hh -> hm -> mh).
// ---------------------------------------------------------------------------
#define BM 128
#define BN 128
#define BK 32
#define STAGES 3
#define KTILES (K_DIM / BK)        // 200
#define SPLIT_SM 8192              // 128 rows x 64 B
#define STAGE_SM (4 * SPLIT_SM)    // 32768 B
#define GEMM_SMEM (STAGES * STAGE_SM)  // 98304 B

#define HS 132                     // h1 smem row stride (floats)

#define SWZ(r, c) (((r) << 6) + (((c) ^ (((r) >> 1) & 3)) << 4))

__global__ __launch_bounds__(256, 2)
void gemm_scan_fused(const float* __restrict__ bias)
{
    extern __shared__ char smem[];
    const uint32_t smb = smem_to_u32(smem);
    const int tid  = threadIdx.x;
    const int wid  = tid >> 5;
    const int lane = tid & 31;
    const int bm = blockIdx.y * BM;
    const int bn = blockIdx.x * BN;
    const int warp_m = (wid >> 2) * 64;
    const int warp_n = (wid & 3) * 32;

    // Compact load plan: 4 running pointers + 4 smem offsets.
    const int r0 = tid >> 2;             // 0..63
    const int cc = tid & 3;
    const __nv_bfloat16* gp0 = g_Ah + (size_t)(bm + r0) * K_DIM + cc * 8;
    const __nv_bfloat16* gp1 = g_Am + (size_t)(bm + r0) * K_DIM + cc * 8;
    const __nv_bfloat16* gp2 = g_Bh + (size_t)(bn + r0) * K_DIM + cc * 8;
    const __nv_bfloat16* gp3 = g_Bm + (size_t)(bn + r0) * K_DIM + cc * 8;
    const uint32_t sw = SWZ(r0, cc);     // SWZ(r0+64,cc) = sw + 4096
    const uint32_t so0 = 0 * SPLIT_SM + sw;
    const uint32_t so1 = 1 * SPLIT_SM + sw;
    const uint32_t so2 = 2 * SPLIT_SM + sw;
    const uint32_t so3 = 3 * SPLIT_SM + sw;
    const size_t ROWOFF = (size_t)64 * K_DIM;   // +64 rows in gmem

#define ISSUE_STAGE(stb) do {                                  \
        cp16((stb) + so0,        gp0);                         \
        cp16((stb) + so0 + 4096, gp0 + ROWOFF);                \
        cp16((stb) + so1,        gp1);                         \
        cp16((stb) + so1 + 4096, gp1 + ROWOFF);                \
        cp16((stb) + so2,        gp2);                         \
        cp16((stb) + so2 + 4096, gp2 + ROWOFF);                \
        cp16((stb) + so3,        gp3);                         \
        cp16((stb) + so3 + 4096, gp3 + ROWOFF);                \
        gp0 += BK; gp1 += BK; gp2 += BK; gp3 += BK;            \
    } while (0)

    float acc[4][4][4];
#pragma unroll
    for (int mt = 0; mt < 4; ++mt)
#pragma unroll
        for (int nt = 0; nt < 4; ++nt)
#pragma unroll
            for (int e = 0; e < 4; ++e) acc[mt][nt][e] = 0.0f;

    // prologue: prefetch stages 0,1
#pragma unroll
    for (int s = 0; s < STAGES - 1; ++s) {
        ISSUE_STAGE(smb + s * STAGE_SM);
        CP_COMMIT();
    }

    const int lr  = lane & 15;
    const int lch = lane >> 4;

    int bc = 0;
    int bp = STAGES - 1;

    for (int kt = 0; kt < KTILES; ++kt) {
        CP_WAIT1();
        __syncthreads();

        if (kt + STAGES - 1 < KTILES) {
            ISSUE_STAGE(smb + bp * STAGE_SM);
        }
        CP_COMMIT();

        const uint32_t stb = smb + bc * STAGE_SM;

#pragma unroll
        for (int k16 = 0; k16 < 2; ++k16) {
            const int c = k16 * 2 + lch;

            uint32_t af[4][4];       // reused: A-hi then A-mid
            uint32_t bh[2][4];
            uint32_t bmf[2][4];

#pragma unroll
            for (int mt = 0; mt < 4; ++mt)
                ldsm4(af[mt], stb + 0 * SPLIT_SM + SWZ(warp_m + mt * 16 + lr, c));
#pragma unroll
            for (int np = 0; np < 2; ++np)
                ldsm4(bh[np],  stb + 2 * SPLIT_SM + SWZ(warp_n + np * 16 + lr, c));
#pragma unroll
            for (int np = 0; np < 2; ++np)
                ldsm4(bmf[np], stb + 3 * SPLIT_SM + SWZ(warp_n + np * 16 + lr, c));

            // pass hh
#pragma unroll
            for (int mt = 0; mt < 4; ++mt)
#pragma unroll
                for (int nt = 0; nt < 4; ++nt) {
                    const int np = nt >> 1, sel = nt & 1;
                    mma16816(acc[mt][nt], af[mt], bh[np][sel], bh[np][sel + 2]);
                }
            // pass hm
#pragma unroll
            for (int mt = 0; mt < 4; ++mt)
#pragma unroll
                for (int nt = 0; nt < 4; ++nt) {
                    const int np = nt >> 1, sel = nt & 1;
                    mma16816(acc[mt][nt], af[mt], bmf[np][sel], bmf[np][sel + 2]);
                }
            // A-mid overwrites af (WAR caps fragment liveness)
#pragma unroll
            for (int mt = 0; mt < 4; ++mt)
                ldsm4(af[mt], stb + 1 * SPLIT_SM + SWZ(warp_m + mt * 16 + lr, c));
            // pass mh
#pragma unroll
            for (int mt = 0; mt < 4; ++mt)
#pragma unroll
                for (int nt = 0; nt < 4; ++nt) {
                    const int np = nt >> 1, sel = nt & 1;
                    mma16816(acc[mt][nt], af[mt], bh[np][sel], bh[np][sel + 2]);
                }
        }

        bc = (bc == STAGES - 1) ? 0 : bc + 1;
        bp = (bp == STAGES - 1) ? 0 : bp + 1;
    }

    // ---- epilogue 1: acc (+bias) -> smem h1 tile [128 m][HS] ----
    __syncthreads();
    float* smh1 = (float*)smem;

    const int lrow = lane >> 2;
    const int lcol = (lane & 3) * 2;
#pragma unroll
    for (int nt = 0; nt < 4; ++nt) {
        const int nl = warp_n + nt * 8 + lcol;
        const int ng = bn + nl;
        const float bx = (ng < N_DIM)     ? bias[ng]     : 0.0f;
        const float by = (ng + 1 < N_DIM) ? bias[ng + 1] : 0.0f;
#pragma unroll
        for (int mt = 0; mt < 4; ++mt) {
            const int m0 = warp_m + mt * 16 + lrow;
            smh1[(size_t)m0 * HS + nl]           = acc[mt][nt][0] + bx;
            smh1[(size_t)m0 * HS + nl + 1]       = acc[mt][nt][1] + by;
            smh1[(size_t)(m0 + 8) * HS + nl]     = acc[mt][nt][2] + bx;
            smh1[(size_t)(m0 + 8) * HS + nl + 1] = acc[mt][nt][3] + by;
        }
    }
    __syncthreads();

    // ---- epilogue 2: fused LIF scan over the 4 batches in this tile ----
    {
        const int hl    = tid & 127;
        const int half  = tid >> 7;
        const int hg    = bn + hl;
        const bool valid = (hg < N_DIM);
        const int b0    = (bm >> 5);

#pragma unroll
        for (int q = 0; q < 2; ++q) {
            const int bq = half * 2 + q;
            const int b  = b0 + bq;
            float mem = 0.0f;
            int flg = 0;
#pragma unroll 4
            for (int t = 0; t < TSTEPS; ++t) {
                const float cur = valid ? smh1[(size_t)(bq * 32 + t) * HS + hl] : 0.0f;
                const float mn  = (mem > THR_F) ? 0.0f : fmaf(BETA_F, mem, cur);
                mem = mn;
                const bool spk = valid && (mn > THR_F);
                if (valid && fabsf(mn - THR_F) < TOL_F) flg = 1;
                const uint32_t bits = __ballot_sync(0xffffffffu, spk);
                if (lane == 0)
                    g_spk1[(size_t)(b * TSTEPS + t) * 32 + (hg >> 5)] = bits;
            }
            if (flg) {
                const int i = atomicAdd(&g_nflag, 1);
                if (i < FLAG_CAP) g_flag[i] = (b << 10) | hg;
            }
        }
    }
#undef ISSUE_STAGE
}

// ---------------------------------------------------------------------------
// Fixup v4: one CTA per flagged (b,h) entry, 1024 threads = 32 warps,
// ONE WARP PER TIMESTEP. W1 row staged to smem once (kills redundant W
// streams); each warp streams only its 25.6 KB x row, unroll 4 for MLP.
// ---------------------------------------------------------------------------
__global__ __launch_bounds__(1024)
void snn_fixup_kernel(const float* __restrict__ X,
                      const float* __restrict__ W1,
                      const float* __restrict__ b1)
{
    __shared__ float sW[K_DIM];          // 25.6 KB
    __shared__ float sdot[TSTEPS];

    const int tid  = threadIdx.x;
    const int lane = tid & 31;
    const int warp = tid >> 5;          // 0..31 == timestep
    int total = g_nflag;
    if (total > FLAG_CAP) total = FLAG_CAP;

    for (int e = blockIdx.x; e < total; e += gridDim.x) {
        const int pair = g_flag[e];
        const int b = pair >> 10;
        const int h = pair & 1023;

        // stage W1 row cooperatively (float4)
        {
            const float4* wr = (const float4*)(W1 + (size_t)h * K_DIM);
            for (int i = tid; i < K_DIM / 4; i += 1024)
                ((float4*)sW)[i] = wr[i];
        }
        __syncthreads();

        const float* xr = X + (size_t)(b * TSTEPS + warp) * K_DIM;
        float s = 0.0f;
#pragma unroll 4
        for (int k = lane * 4; k < K_DIM; k += 128) {
            const float4 xv = *(const float4*)(xr + k);
            const float4 wv = *(const float4*)(sW + k);
            s = fmaf(xv.x, wv.x, s);
            s = fmaf(xv.y, wv.y, s);
            s = fmaf(xv.z, wv.z, s);
            s = fmaf(xv.w, wv.w, s);
        }
#pragma unroll
        for (int o = 16; o; o >>= 1)
            s += __shfl_xor_sync(0xffffffffu, s, o);
        if (lane == 0) sdot[warp] = s;
        __syncthreads();

        if (tid == 0) {
            const float bv = b1[h];
            const uint32_t bit = 1u << (h & 31);
            float mem = 0.0f;
            for (int t = 0; t < TSTEPS; t++) {
                const float cur = sdot[t] + bv;
                const float mn  = (mem > THR_F) ? 0.0f : fmaf(BETA_F, mem, cur);
                mem = mn;
                uint32_t* wptr = &g_spk1[(size_t)(b * TSTEPS + t) * 32 + (h >> 5)];
                if (mn > THR_F) atomicOr(wptr, bit);
                else            atomicAnd(wptr, ~bit);
            }
        }
        __syncthreads();
    }
}

// ---------------------------------------------------------------------------
// Layer-2 (t-parallel): spk1 bits + W2 staged to smem, 8 warps x 4 timesteps
// compute h2 dots (bit-test); thread 0 runs the LIF scan.
// ---------------------------------------------------------------------------
__global__ __launch_bounds__(256)
void snn_layer2_kernel(const float* __restrict__ W2,
                       const float* __restrict__ b2,
                       float* __restrict__ out)
{
    __shared__ float    sW2[ACT][HID];
    __shared__ uint32_t sbits[TSTEPS][32];
    __shared__ float    sdot[TSTEPS][ACT];

    const int b    = blockIdx.x;
    const int tid  = threadIdx.x;
    const int lane = tid & 31;
    const int warp = tid >> 5;          // 0..7

    for (int i = tid; i < ACT * HID; i += 256)
        sW2[i / HID][i % HID] = W2[i];
    for (int i = tid; i < TSTEPS * 32; i += 256)
        sbits[i >> 5][i & 31] = g_spk1[(size_t)(b * TSTEPS + (i >> 5)) * 32 + (i & 31)];
    __syncthreads();

#pragma unroll
    for (int q = 0; q < 4; ++q) {
        const int t = warp * 4 + q;
        float a0 = 0.f, a1 = 0.f, a2 = 0.f, a3 = 0.f;
#pragma unroll 4
        for (int j = 0; j < 32; ++j) {
            const int h = j * 32 + lane;
            if (h < HID && ((sbits[t][j] >> lane) & 1u)) {
                a0 += sW2[0][h]; a1 += sW2[1][h];
                a2 += sW2[2][h]; a3 += sW2[3][h];
            }
        }
#pragma unroll
        for (int o = 16; o; o >>= 1) {
            a0 += __shfl_xor_sync(0xffffffffu, a0, o);
            a1 += __shfl_xor_sync(0xffffffffu, a1, o);
            a2 += __shfl_xor_sync(0xffffffffu, a2, o);
            a3 += __shfl_xor_sync(0xffffffffu, a3, o);
        }
        if (lane == 0) {
            sdot[t][0] = a0; sdot[t][1] = a1;
            sdot[t][2] = a2; sdot[t][3] = a3;
        }
    }
    __syncthreads();

    if (tid == 0) {
        float m2[ACT] = {0.f, 0.f, 0.f, 0.f};
        for (int t = 0; t < TSTEPS; t++) {
#pragma unroll
            for (int a = 0; a < ACT; a++) {
                const float h2 = sdot[t][a] + b2[a];
                const float mn = (m2[a] > THR_F) ? 0.0f : fmaf(BETA_F, m2[a], h2);
                m2[a] = mn;
                out[((size_t)(b * TSTEPS + t)) * ACT + a] = (mn > THR_F) ? 1.0f : 0.0f;
            }
        }
    }
}

// ---------------------------------------------------------------------------
extern "C" void kernel_launch(void* const* d_in, const int* in_sizes, int n_in,
                              void* d_out, int out_size)
{
    const float* x  = (const float*)d_in[0];   // [128,32,6400]
    const float* W1 = (const float*)d_in[1];   // [1000,6400]
    const float* b1 = (const float*)d_in[2];   // [1000]
    const float* W2 = (const float*)d_in[3];   // [4,1000]
    const float* b2 = (const float*)d_in[4];   // [4]
    float* out = (float*)d_out;                // [128,32,4]

    cudaFuncSetAttribute(gemm_scan_fused,
                         cudaFuncAttributeMaxDynamicSharedMemorySize, GEMM_SMEM);

    {   // single vectorized split pass: X then W1 (padded); resets flag counter
        const int ngroups = XGRP + WGRP;
        split_kernel<<<(ngroups + 255) / 256, 256>>>(x, W1);
    }

    dim3 grid(N_PAD / BN, M_DIM / BM);         // (8, 32)
    gemm_scan_fused<<<grid, 256, GEMM_SMEM>>>(b1);

    snn_fixup_kernel<<<512, 1024>>>(x, W1, b1);
    snn_layer2_kernel<<<BATCH, 256>>>(W2, b2, out);
}